// round 15
// baseline (speedup 1.0000x reference)
#include <cuda_runtime.h>
#include <cuda_fp16.h>
#include <cstdint>
#include <math.h>

// ---------------- problem constants ----------------
#define N_IMG 16
#define CI    64
#define HW    224
#define PLANE (HW*HW)       // 50176
#define CO    128
#define OH    222
#define OW    222
#define KPOS  9
#define KTOT  (CI*KPOS)     // 576

// ---------------- config ----------------
#define THREADS 384
#define NWARPS  12
#define NSM 152                          // GB300 has 152 SMs
#define TILES_TOTAL (N_IMG*OH*2)         // 7104

// W smem: [co 128][k 576 pad 584] fp16, row stride 1168B (conflict-free)
#define WK_PAD   584
#define W_ROWB   (WK_PAD*2)              // 1168
#define OFF_W    0
#define W_BYTES  (CO*W_ROWB)             // 149504

// S smem: ring of 4 planes, plane = [col 132][ci 64 pad 72] fp16
#define S_CIPAD  72
#define S_COLB   (S_CIPAD*2)             // 144
#define S_PLANEB (132*S_COLB)            // 19008
#define OFF_S    W_BYTES                 // 149504
#define S_BYTES  (4*S_PLANEB)            // 76032

#define OFF_BIAS (OFF_S + S_BYTES)       // 225536
#define OFF_MIN  (OFF_BIAS + 512)        // 226048 (256 floats)
#define SMEM_TOTAL (OFF_MIN + 1024)      // 227072

// named barriers
#define BAR_ALL()        asm volatile("bar.sync 1, %0;" :: "n"(THREADS) : "memory")
#define BAR_PAIR(idx)    asm volatile("bar.sync %0, 64;" :: "r"(3 + (idx)) : "memory")

// ---------------- PTX helpers ----------------
__device__ __forceinline__ uint32_t smem_u32(const void* p) {
    uint32_t a;
    asm("{ .reg .u64 t; cvta.to.shared.u64 t, %1; cvt.u32.u64 %0, t; }" : "=r"(a) : "l"(p));
    return a;
}

#define LDSM_X4(r, addr) \
    asm volatile("ldmatrix.sync.aligned.m8n8.x4.shared.b16 {%0,%1,%2,%3}, [%4];" \
        : "=r"((r)[0]), "=r"((r)[1]), "=r"((r)[2]), "=r"((r)[3]) : "r"(addr))

__device__ __forceinline__ void mma_f16(uint32_t* d, const uint32_t* a, const uint32_t* b) {
    asm volatile("mma.sync.aligned.m16n8k16.row.col.f16.f16.f16.f16 "
        "{%0,%1}, {%2,%3,%4,%5}, {%6,%7}, {%0,%1};"
        : "+r"(d[0]), "+r"(d[1])
        : "r"(a[0]), "r"(a[1]), "r"(a[2]), "r"(a[3]), "r"(b[0]), "r"(b[1]));
}

__device__ __forceinline__ uint32_t pack_h16(float lo, float hi) {
    __half2 t = __floats2half2_rn(lo, hi);
    return *(uint32_t*)&t;
}

// ---------------- one staging task: oct (8 ci), 32 cols ----------------
__device__ __forceinline__ void stage_task(
    const float* __restrict__ x, int n, int r_in, int ow0,
    int oct, int cg, int lane, uint32_t sb)
{
    int col = cg * 32 + lane;
    bool stv = (col < 132);
    bool ldv = stv && (ow0 + col < HW);
    const float* gp = x + ((size_t)n * CI + oct * 8) * PLANE
                        + (size_t)r_in * HW + (ow0 + col);
    float v[8];
    #pragma unroll
    for (int q = 0; q < 8; ++q) v[q] = ldv ? gp[(size_t)q * PLANE] : 0.0f;
    if (stv) {
        uint32_t pk0 = pack_h16(v[0], v[1]);
        uint32_t pk1 = pack_h16(v[2], v[3]);
        uint32_t pk2 = pack_h16(v[4], v[5]);
        uint32_t pk3 = pack_h16(v[6], v[7]);
        uint32_t sa = sb + OFF_S + (uint32_t)(r_in & 3) * S_PLANEB
                    + (uint32_t)col * S_COLB + (uint32_t)oct * 16;
        asm volatile("st.shared.v4.b32 [%0], {%1,%2,%3,%4};"
                     :: "r"(sa), "r"(pk0), "r"(pk1), "r"(pk2), "r"(pk3));
    }
}

// ---------------- kernel ----------------
__global__ __launch_bounds__(THREADS, 1)
void conv_min_tanh_ur(const float* __restrict__ x,
                      const float* __restrict__ wgt,
                      const float* __restrict__ bias,
                      float* __restrict__ out)
{
    extern __shared__ char smem[];
    const uint32_t sb = smem_u32(smem);
    const int tid  = threadIdx.x;
    const int lane = tid & 31;
    const int wid  = tid >> 5;
    const bool consumer = (wid < 8);
    const int wm   = wid & 3;        // consumer: pixel group (32 px)
    const int wn   = (wid >> 2) & 1; // consumer: co half (64 co)
    __half2* bias_sm = (__half2*)(smem + OFF_BIAS);
    float*   min_sm  = (float*)(smem + OFF_MIN);

    // ---- stage weights once (vectorized float4 loads) ----
    for (int i4 = tid; i4 < (CO * KTOT) / 4; i4 += THREADS) {
        float4 w4 = ((const float4*)wgt)[i4];
        int base = i4 * 4;
        int co   = base / KTOT;
        int rem  = base - co * KTOT;
        float vv[4] = {w4.x, w4.y, w4.z, w4.w};
        #pragma unroll
        for (int j = 0; j < 4; ++j) {
            int r2 = rem + j;
            int ci = r2 / KPOS;
            int kp = r2 - ci * KPOS;
            int k  = kp * 64 + ci;
            *(__half*)(smem + OFF_W + co * W_ROWB + k * 2) = __float2half_rn(vv[j]);
        }
    }
    if (tid < CO / 2) {
        bias_sm[tid] = __floats2half2_rn(bias[2 * tid], bias[2 * tid + 1]);
    }
    __syncthreads();

    // per-thread bias regs: co pair = wn*64 + nt*8 + 2*(lane&3)
    __half2 bh[8];
    #pragma unroll
    for (int nt = 0; nt < 8; ++nt) {
        int c = wn * 32 + nt * 4 + (lane & 3);
        bh[nt] = bias_sm[c];
    }

    // ldmatrix lane address components
    const uint32_t aCol = (uint32_t)(wm * 32 + (lane & 15)) * S_COLB
                        + (uint32_t)(lane >> 4) * 16;
    const uint32_t bBase = sb + OFF_W
        + (uint32_t)(wn * 64 + (lane & 7) + ((lane >> 4) & 1) * 8) * W_ROWB
        + (uint32_t)((lane >> 3) & 1) * 16;

    // prorated contiguous tile range over 152 CTAs
    const int tStart = (int)(((long long)blockIdx.x * TILES_TOTAL) / NSM);
    const int tEnd   = (int)(((long long)(blockIdx.x + 1) * TILES_TOTAL) / NSM);

    int prev_strip = -1;

    for (int t = tStart; t < tEnd; ++t) {
        const int strip = t / OH;              // 0..31 : (n, half)
        const int oh    = t - strip * OH;      // row within strip
        const int n     = strip >> 1;
        const int ow0   = (strip & 1) ? (OW - 128) : 0;

        // ---- strip entry: stage planes oh..oh+2 (120 tasks, 12 warps) ----
        if (strip != prev_strip) {
            #pragma unroll 1
            for (int j = 0; j < 10; ++j) {
                int tk = wid + NWARPS * j;
                if (tk >= 120) break;
                int pl  = tk / 40;
                int r   = tk - pl * 40;
                int oct = r / 5;
                int cg  = r - oct * 5;
                stage_task(x, n, oh + pl, ow0, oct, cg, lane, sb);
            }
            BAR_ALL();
            prev_strip = strip;
        }
        // invariant: planes oh, oh+1, oh+2 staged & visible

        const bool next_same = (t + 1 < tEnd) && (oh + 1 < OH);

        if (consumer) {
            // ---- MMA: warp tile 32px x 64co; kp FULLY UNROLLED ----
            uint32_t acc[2][8][2];
            #pragma unroll
            for (int mi = 0; mi < 2; ++mi)
                #pragma unroll
                for (int nt = 0; nt < 8; ++nt) {
                    acc[mi][nt][0] = 0u;
                    acc[mi][nt][1] = 0u;
                }

            #pragma unroll
            for (int kp = 0; kp < KPOS; ++kp) {
                const int kh = kp / 3, kw = kp - 3 * (kp / 3);
                const uint32_t aKp = sb + OFF_S + (uint32_t)((oh + kh) & 3) * S_PLANEB
                                   + aCol + (uint32_t)kw * S_COLB;
                const uint32_t kB  = (uint32_t)(kp * 64) * 2;
                #pragma unroll
                for (int ks = 0; ks < 4; ++ks) {
                    uint32_t a0[4], a1[4];
                    LDSM_X4(a0, aKp + ks * 32);
                    LDSM_X4(a1, aKp + ks * 32 + 16 * S_COLB);
                    uint32_t bf[4][4];
                    #pragma unroll
                    for (int ntp = 0; ntp < 4; ++ntp)
                        LDSM_X4(bf[ntp], bBase + (uint32_t)ntp * 16 * W_ROWB + kB + ks * 32);
                    #pragma unroll
                    for (int ntp = 0; ntp < 4; ++ntp) {
                        mma_f16(acc[0][2 * ntp + 0], a0, &bf[ntp][0]);
                        mma_f16(acc[0][2 * ntp + 1], a0, &bf[ntp][2]);
                        mma_f16(acc[1][2 * ntp + 0], a1, &bf[ntp][0]);
                        mma_f16(acc[1][2 * ntp + 1], a1, &bf[ntp][2]);
                    }
                }
            }

            // ---- epilogue: half2 bias + min over this warp's 64 co ----
            float v4[4];  // [mi*2 + h]
            #pragma unroll
            for (int mi = 0; mi < 2; ++mi) {
                __half2 h0 = __floats2half2_rn(6.5e4f, 6.5e4f);
                __half2 h1 = h0;
                #pragma unroll
                for (int nt = 0; nt < 8; ++nt) {
                    h0 = __hmin2(h0, __hadd2(*(__half2*)&acc[mi][nt][0], bh[nt]));
                    h1 = __hmin2(h1, __hadd2(*(__half2*)&acc[mi][nt][1], bh[nt]));
                }
                float2 f0 = __half22float2(h0);
                float2 f1 = __half22float2(h1);
                v4[mi * 2 + 0] = fminf(f0.x, f0.y);
                v4[mi * 2 + 1] = fminf(f1.x, f1.y);
            }
            #pragma unroll
            for (int j = 0; j < 4; ++j) {
                v4[j] = fminf(v4[j], __shfl_xor_sync(0xFFFFFFFFu, v4[j], 1));
                v4[j] = fminf(v4[j], __shfl_xor_sync(0xFFFFFFFFu, v4[j], 2));
            }
            if ((lane & 3) == 0) {
                int row = lane >> 2;
                #pragma unroll
                for (int mi = 0; mi < 2; ++mi) {
                    int px0 = wm * 32 + mi * 16 + row;
                    min_sm[px0 * 2 + wn]       = v4[mi * 2 + 0];
                    min_sm[(px0 + 8) * 2 + wn] = v4[mi * 2 + 1];
                }
            }
            // pair barrier: only the two co-half warps of this pixel group
            BAR_PAIR(wm);
            {
                // split the 32 output pixels between the two pair warps
                int px = wm * 32 + wn * 16 + (lane & 15);
                if (lane < 16 || wn == wn) { /* all lanes participate via mapping below */ }
                if (lane < 16) {
                    float2 q = *(const float2*)(min_sm + px * 2);
                    float m = fminf(q.x, q.y);
                    out[((size_t)n * OH + oh) * OW + ow0 + px] = tanhf(tanhf(m));
                }
            }
        } else {
            // ---- producers (4 warps): stage plane oh+3 (10 tasks/warp) ----
            if (next_same) {
                const int pw = wid - 8;
                #pragma unroll
                for (int j = 0; j < 10; ++j) {
                    int tk  = pw + 4 * j;     // 0..39
                    int oct = tk / 5;
                    int cg  = tk - oct * 5;
                    stage_task(x, n, oh + 3, ow0, oct, cg, lane, sb);
                }
            }
        }

        BAR_ALL();  // plane oh+3 visible; min_sm reads done; ring slot retire
    }
}

extern "C" void kernel_launch(void* const* d_in, const int* in_sizes, int n_in,
                              void* d_out, int out_size)
{
    const float* x    = (const float*)d_in[0];
    const float* wgt  = (const float*)d_in[1];
    const float* bias = (const float*)d_in[2];
    float* out        = (float*)d_out;

    cudaFuncSetAttribute(conv_min_tanh_ur,
                         cudaFuncAttributeMaxDynamicSharedMemorySize, SMEM_TOTAL);
    conv_min_tanh_ur<<<NSM, THREADS, SMEM_TOTAL>>>(x, wgt, bias, out);
}

// round 16
// speedup vs baseline: 1.4384x; 1.4384x over previous
#include <cuda_runtime.h>
#include <cuda_fp16.h>
#include <cstdint>
#include <math.h>

// ---------------- problem constants ----------------
#define N_IMG 16
#define CI    64
#define HW    224
#define PLANE (HW*HW)       // 50176
#define CO    128
#define OH    222
#define OW    222
#define KPOS  9
#define KTOT  (CI*KPOS)     // 576

// ---------------- config ----------------
#define THREADS 384
#define NWARPS  12
#define NSM 152                          // GB300 has 152 SMs
#define TILES_TOTAL (N_IMG*OH*2)         // 7104

// W smem: [co 128][k 576 pad 584] fp16, row stride 1168B (conflict-free)
#define WK_PAD   584
#define W_ROWB   (WK_PAD*2)              // 1168
#define OFF_W    0
#define W_BYTES  (CO*W_ROWB)             // 149504

// S smem: ring of 4 planes, plane = [col 132][ci 64 pad 72] fp16
#define S_CIPAD  72
#define S_COLB   (S_CIPAD*2)             // 144
#define S_PLANEB (132*S_COLB)            // 19008
#define OFF_S    W_BYTES                 // 149504
#define S_BYTES  (4*S_PLANEB)            // 76032

#define OFF_BIAS (OFF_S + S_BYTES)       // 225536
#define OFF_MIN  (OFF_BIAS + 512)        // 226048 (256 floats)
#define SMEM_TOTAL (OFF_MIN + 1024)      // 227072

// named barriers
#define BAR_ALL()        asm volatile("bar.sync 1, %0;" :: "n"(THREADS) : "memory")
#define BAR_PAIR(idx)    asm volatile("bar.sync %0, 64;" :: "r"(3 + (idx)) : "memory")

// ---------------- PTX helpers ----------------
__device__ __forceinline__ uint32_t smem_u32(const void* p) {
    uint32_t a;
    asm("{ .reg .u64 t; cvta.to.shared.u64 t, %1; cvt.u32.u64 %0, t; }" : "=r"(a) : "l"(p));
    return a;
}

#define LDSM_X4(r, addr) \
    asm volatile("ldmatrix.sync.aligned.m8n8.x4.shared.b16 {%0,%1,%2,%3}, [%4];" \
        : "=r"((r)[0]), "=r"((r)[1]), "=r"((r)[2]), "=r"((r)[3]) : "r"(addr))

__device__ __forceinline__ void mma_f16(uint32_t* d, const uint32_t* a, const uint32_t* b) {
    asm volatile("mma.sync.aligned.m16n8k16.row.col.f16.f16.f16.f16 "
        "{%0,%1}, {%2,%3,%4,%5}, {%6,%7}, {%0,%1};"
        : "+r"(d[0]), "+r"(d[1])
        : "r"(a[0]), "r"(a[1]), "r"(a[2]), "r"(a[3]), "r"(b[0]), "r"(b[1]));
}

__device__ __forceinline__ uint32_t pack_h16(float lo, float hi) {
    __half2 t = __floats2half2_rn(lo, hi);
    return *(uint32_t*)&t;
}

// ---------------- one staging task: oct (8 ci), 32 cols ----------------
__device__ __forceinline__ void stage_task(
    const float* __restrict__ x, int n, int r_in, int ow0,
    int oct, int cg, int lane, uint32_t sb)
{
    int col = cg * 32 + lane;
    bool stv = (col < 132);
    bool ldv = stv && (ow0 + col < HW);
    const float* gp = x + ((size_t)n * CI + oct * 8) * PLANE
                        + (size_t)r_in * HW + (ow0 + col);
    float v[8];
    #pragma unroll
    for (int q = 0; q < 8; ++q) v[q] = ldv ? gp[(size_t)q * PLANE] : 0.0f;
    if (stv) {
        uint32_t pk0 = pack_h16(v[0], v[1]);
        uint32_t pk1 = pack_h16(v[2], v[3]);
        uint32_t pk2 = pack_h16(v[4], v[5]);
        uint32_t pk3 = pack_h16(v[6], v[7]);
        uint32_t sa = sb + OFF_S + (uint32_t)(r_in & 3) * S_PLANEB
                    + (uint32_t)col * S_COLB + (uint32_t)oct * 16;
        asm volatile("st.shared.v4.b32 [%0], {%1,%2,%3,%4};"
                     :: "r"(sa), "r"(pk0), "r"(pk1), "r"(pk2), "r"(pk3));
    }
}

// ---------------- kernel ----------------
__global__ __launch_bounds__(THREADS, 1)
void conv_min_tanh_v16(const float* __restrict__ x,
                       const float* __restrict__ wgt,
                       const float* __restrict__ bias,
                       float* __restrict__ out)
{
    extern __shared__ char smem[];
    const uint32_t sb = smem_u32(smem);
    const int tid  = threadIdx.x;
    const int lane = tid & 31;
    const int wid  = tid >> 5;
    const bool consumer = (wid < 8);
    const int wm   = wid & 3;        // consumer: pixel group (32 px)
    const int wn   = (wid >> 2) & 1; // consumer: co half (64 co)
    __half2* bias_sm = (__half2*)(smem + OFF_BIAS);
    float*   min_sm  = (float*)(smem + OFF_MIN);

    // ---- stage weights once (vectorized float4 loads) ----
    for (int i4 = tid; i4 < (CO * KTOT) / 4; i4 += THREADS) {
        float4 w4 = ((const float4*)wgt)[i4];
        int base = i4 * 4;
        int co   = base / KTOT;
        int rem  = base - co * KTOT;
        float vv[4] = {w4.x, w4.y, w4.z, w4.w};
        #pragma unroll
        for (int j = 0; j < 4; ++j) {
            int r2 = rem + j;
            int ci = r2 / KPOS;
            int kp = r2 - ci * KPOS;
            int k  = kp * 64 + ci;
            *(__half*)(smem + OFF_W + co * W_ROWB + k * 2) = __float2half_rn(vv[j]);
        }
    }
    if (tid < CO / 2) {
        bias_sm[tid] = __floats2half2_rn(bias[2 * tid], bias[2 * tid + 1]);
    }
    __syncthreads();

    // per-thread bias regs: co pair = wn*64 + nt*8 + 2*(lane&3)
    __half2 bh[8];
    #pragma unroll
    for (int nt = 0; nt < 8; ++nt) {
        int c = wn * 32 + nt * 4 + (lane & 3);
        bh[nt] = bias_sm[c];
    }

    // ldmatrix lane address components
    const uint32_t aCol = (uint32_t)(wm * 32 + (lane & 15)) * S_COLB
                        + (uint32_t)(lane >> 4) * 16;
    const uint32_t bBase = sb + OFF_W
        + (uint32_t)(wn * 64 + (lane & 7) + ((lane >> 4) & 1) * 8) * W_ROWB
        + (uint32_t)((lane >> 3) & 1) * 16;

    // prorated contiguous tile range over 152 CTAs
    const int tStart = (int)(((long long)blockIdx.x * TILES_TOTAL) / NSM);
    const int tEnd   = (int)(((long long)(blockIdx.x + 1) * TILES_TOTAL) / NSM);

    int prev_strip = -1;

    for (int t = tStart; t < tEnd; ++t) {
        const int strip = t / OH;              // 0..31 : (n, half)
        const int oh    = t - strip * OH;      // row within strip
        const int n     = strip >> 1;
        const int ow0   = (strip & 1) ? (OW - 128) : 0;

        // ---- strip entry: stage planes oh..oh+2 (120 tasks, 12 warps) ----
        if (strip != prev_strip) {
            #pragma unroll 1
            for (int j = 0; j < 10; ++j) {
                int tk = wid + NWARPS * j;
                if (tk >= 120) break;
                int pl  = tk / 40;
                int r   = tk - pl * 40;
                int oct = r / 5;
                int cg  = r - oct * 5;
                stage_task(x, n, oh + pl, ow0, oct, cg, lane, sb);
            }
            BAR_ALL();
            prev_strip = strip;
        }
        // invariant: planes oh, oh+1, oh+2 staged & visible

        const bool next_same = (t + 1 < tEnd) && (oh + 1 < OH);

        if (consumer) {
            // ---- MMA: warp tile 32px x 64co; kp loop NOT unrolled (L0-resident) ----
            uint32_t acc[2][8][2];
            #pragma unroll
            for (int mi = 0; mi < 2; ++mi)
                #pragma unroll
                for (int nt = 0; nt < 8; ++nt) {
                    acc[mi][nt][0] = 0u;
                    acc[mi][nt][1] = 0u;
                }

            #pragma unroll 1
            for (int kp = 0; kp < KPOS; ++kp) {
                const int kh = kp / 3, kw = kp - 3 * (kp / 3);
                const uint32_t aKp = sb + OFF_S + (uint32_t)((oh + kh) & 3) * S_PLANEB
                                   + aCol + (uint32_t)kw * S_COLB;
                const uint32_t kB  = (uint32_t)(kp * 64) * 2;
                #pragma unroll
                for (int ks = 0; ks < 4; ++ks) {
                    uint32_t a0[4], a1[4];
                    LDSM_X4(a0, aKp + ks * 32);
                    LDSM_X4(a1, aKp + ks * 32 + 16 * S_COLB);
                    uint32_t bf[4][4];
                    #pragma unroll
                    for (int ntp = 0; ntp < 4; ++ntp)
                        LDSM_X4(bf[ntp], bBase + (uint32_t)ntp * 16 * W_ROWB + kB + ks * 32);
                    #pragma unroll
                    for (int ntp = 0; ntp < 4; ++ntp) {
                        mma_f16(acc[0][2 * ntp + 0], a0, &bf[ntp][0]);
                        mma_f16(acc[0][2 * ntp + 1], a0, &bf[ntp][2]);
                        mma_f16(acc[1][2 * ntp + 0], a1, &bf[ntp][0]);
                        mma_f16(acc[1][2 * ntp + 1], a1, &bf[ntp][2]);
                    }
                }
            }

            // ---- epilogue: half2 bias + min over this warp's 64 co ----
            float v4[4];  // [mi*2 + h]
            #pragma unroll
            for (int mi = 0; mi < 2; ++mi) {
                __half2 h0 = __floats2half2_rn(6.5e4f, 6.5e4f);
                __half2 h1 = h0;
                #pragma unroll
                for (int nt = 0; nt < 8; ++nt) {
                    h0 = __hmin2(h0, __hadd2(*(__half2*)&acc[mi][nt][0], bh[nt]));
                    h1 = __hmin2(h1, __hadd2(*(__half2*)&acc[mi][nt][1], bh[nt]));
                }
                float2 f0 = __half22float2(h0);
                float2 f1 = __half22float2(h1);
                v4[mi * 2 + 0] = fminf(f0.x, f0.y);
                v4[mi * 2 + 1] = fminf(f1.x, f1.y);
            }
            #pragma unroll
            for (int j = 0; j < 4; ++j) {
                v4[j] = fminf(v4[j], __shfl_xor_sync(0xFFFFFFFFu, v4[j], 1));
                v4[j] = fminf(v4[j], __shfl_xor_sync(0xFFFFFFFFu, v4[j], 2));
            }
            if ((lane & 3) == 0) {
                int row = lane >> 2;
                #pragma unroll
                for (int mi = 0; mi < 2; ++mi) {
                    int px0 = wm * 32 + mi * 16 + row;
                    min_sm[px0 * 2 + wn]       = v4[mi * 2 + 0];
                    min_sm[(px0 + 8) * 2 + wn] = v4[mi * 2 + 1];
                }
            }
            // pair barrier: only the two co-half warps of this pixel group
            BAR_PAIR(wm);
            // split the 32 output pixels between the two pair warps (16 each)
            if (lane < 16) {
                int px = wm * 32 + wn * 16 + lane;
                float2 q = *(const float2*)(min_sm + px * 2);
                float m = fminf(q.x, q.y);
                out[((size_t)n * OH + oh) * OW + ow0 + px] = tanhf(tanhf(m));
            }
        } else {
            // ---- producers (4 warps): stage plane oh+3 (10 tasks/warp) ----
            // slot (oh+3)&3 held plane oh-1; its last readers were in row oh-1.
            if (next_same) {
                const int pw = wid - 8;
                #pragma unroll
                for (int j = 0; j < 10; ++j) {
                    int tk  = pw + 4 * j;     // 0..39
                    int oct = tk / 5;
                    int cg  = tk - oct * 5;
                    stage_task(x, n, oh + 3, ow0, oct, cg, lane, sb);
                }
            }
        }

        BAR_ALL();  // plane oh+3 visible; min_sm reads done; ring slot retire
    }
}

extern "C" void kernel_launch(void* const* d_in, const int* in_sizes, int n_in,
                              void* d_out, int out_size)
{
    const float* x    = (const float*)d_in[0];
    const float* wgt  = (const float*)d_in[1];
    const float* bias = (const float*)d_in[2];
    float* out        = (float*)d_out;

    cudaFuncSetAttribute(conv_min_tanh_v16,
                         cudaFuncAttributeMaxDynamicSharedMemorySize, SMEM_TOTAL);
    conv_min_tanh_v16<<<NSM, THREADS, SMEM_TOTAL>>>(x, wgt, bias, out);
}

// round 17
// speedup vs baseline: 1.4498x; 1.0079x over previous
#include <cuda_runtime.h>
#include <cuda_fp16.h>
#include <cstdint>
#include <math.h>

// ---------------- problem constants ----------------
#define N_IMG 16
#define CI    64
#define HW    224
#define PLANE (HW*HW)       // 50176
#define CO    128
#define OH    222
#define OW    222
#define KPOS  9
#define KTOT  (CI*KPOS)     // 576

// ---------------- config ----------------
#define THREADS 384
#define NWARPS  12
#define NSM 152                          // GB300 has 152 SMs
#define TILES_TOTAL (N_IMG*OH*2)         // 7104

// W smem: [co 128][k 576 pad 584] fp16, row stride 1168B (conflict-free)
#define WK_PAD   584
#define W_ROWB   (WK_PAD*2)              // 1168
#define OFF_W    0
#define W_BYTES  (CO*W_ROWB)             // 149504

// S smem: ring of 4 planes, plane = [col 132][ci 64 pad 72] fp16
#define S_CIPAD  72
#define S_COLB   (S_CIPAD*2)             // 144
#define S_PLANEB (132*S_COLB)            // 19008
#define OFF_S    W_BYTES                 // 149504
#define S_BYTES  (4*S_PLANEB)            // 76032

#define OFF_BIAS (OFF_S + S_BYTES)       // 225536
#define OFF_MIN  (OFF_BIAS + 512)        // 226048 (256 floats)
#define SMEM_TOTAL (OFF_MIN + 1024)      // 227072

// named barriers
#define BAR_ALL()        asm volatile("bar.sync 1, %0;" :: "n"(THREADS) : "memory")
#define BAR_PAIR(idx)    asm volatile("bar.sync %0, 64;" :: "r"(3 + (idx)) : "memory")

// ---------------- PTX helpers ----------------
__device__ __forceinline__ uint32_t smem_u32(const void* p) {
    uint32_t a;
    asm("{ .reg .u64 t; cvta.to.shared.u64 t, %1; cvt.u32.u64 %0, t; }" : "=r"(a) : "l"(p));
    return a;
}

#define LDSM_X4(r, addr) \
    asm volatile("ldmatrix.sync.aligned.m8n8.x4.shared.b16 {%0,%1,%2,%3}, [%4];" \
        : "=r"((r)[0]), "=r"((r)[1]), "=r"((r)[2]), "=r"((r)[3]) : "r"(addr))

__device__ __forceinline__ void mma_f16(uint32_t* d, const uint32_t* a, const uint32_t* b) {
    asm volatile("mma.sync.aligned.m16n8k16.row.col.f16.f16.f16.f16 "
        "{%0,%1}, {%2,%3,%4,%5}, {%6,%7}, {%0,%1};"
        : "+r"(d[0]), "+r"(d[1])
        : "r"(a[0]), "r"(a[1]), "r"(a[2]), "r"(a[3]), "r"(b[0]), "r"(b[1]));
}

__device__ __forceinline__ uint32_t pack_h16(float lo, float hi) {
    __half2 t = __floats2half2_rn(lo, hi);
    return *(uint32_t*)&t;
}

// ---------------- one staging task: oct (8 ci), 32 cols ----------------
__device__ __forceinline__ void stage_task(
    const float* __restrict__ x, int n, int r_in, int ow0,
    int oct, int cg, int lane, uint32_t sb)
{
    int col = cg * 32 + lane;
    bool stv = (col < 132);
    bool ldv = stv && (ow0 + col < HW);
    const float* gp = x + ((size_t)n * CI + oct * 8) * PLANE
                        + (size_t)r_in * HW + (ow0 + col);
    float v[8];
    #pragma unroll
    for (int q = 0; q < 8; ++q) v[q] = ldv ? gp[(size_t)q * PLANE] : 0.0f;
    if (stv) {
        uint32_t pk0 = pack_h16(v[0], v[1]);
        uint32_t pk1 = pack_h16(v[2], v[3]);
        uint32_t pk2 = pack_h16(v[4], v[5]);
        uint32_t pk3 = pack_h16(v[6], v[7]);
        uint32_t sa = sb + OFF_S + (uint32_t)(r_in & 3) * S_PLANEB
                    + (uint32_t)col * S_COLB + (uint32_t)oct * 16;
        asm volatile("st.shared.v4.b32 [%0], {%1,%2,%3,%4};"
                     :: "r"(sa), "r"(pk0), "r"(pk1), "r"(pk2), "r"(pk3));
    }
}

// ---------------- kernel ----------------
__global__ __launch_bounds__(THREADS, 1)
void conv_min_tanh_sp(const float* __restrict__ x,
                      const float* __restrict__ wgt,
                      const float* __restrict__ bias,
                      float* __restrict__ out)
{
    extern __shared__ char smem[];
    const uint32_t sb = smem_u32(smem);
    const int tid  = threadIdx.x;
    const int lane = tid & 31;
    const int wid  = tid >> 5;
    const bool consumer = (wid < 8);
    const int wm   = wid & 3;        // consumer: pixel group (32 px)
    const int wn   = (wid >> 2) & 1; // consumer: co half (64 co)
    __half2* bias_sm = (__half2*)(smem + OFF_BIAS);
    float*   min_sm  = (float*)(smem + OFF_MIN);

    // ---- stage weights once (vectorized float4 loads) ----
    for (int i4 = tid; i4 < (CO * KTOT) / 4; i4 += THREADS) {
        float4 w4 = ((const float4*)wgt)[i4];
        int base = i4 * 4;
        int co   = base / KTOT;
        int rem  = base - co * KTOT;
        float vv[4] = {w4.x, w4.y, w4.z, w4.w};
        #pragma unroll
        for (int j = 0; j < 4; ++j) {
            int r2 = rem + j;
            int ci = r2 / KPOS;
            int kp = r2 - ci * KPOS;
            int k  = kp * 64 + ci;
            *(__half*)(smem + OFF_W + co * W_ROWB + k * 2) = __float2half_rn(vv[j]);
        }
    }
    if (tid < CO / 2) {
        bias_sm[tid] = __floats2half2_rn(bias[2 * tid], bias[2 * tid + 1]);
    }
    __syncthreads();

    // per-thread bias regs: co pair = wn*64 + nt*8 + 2*(lane&3)
    __half2 bh[8];
    #pragma unroll
    for (int nt = 0; nt < 8; ++nt) {
        int c = wn * 32 + nt * 4 + (lane & 3);
        bh[nt] = bias_sm[c];
    }

    // ldmatrix lane address components
    const uint32_t aCol = (uint32_t)(wm * 32 + (lane & 15)) * S_COLB
                        + (uint32_t)(lane >> 4) * 16;
    const uint32_t bBase = sb + OFF_W
        + (uint32_t)(wn * 64 + (lane & 7) + ((lane >> 4) & 1) * 8) * W_ROWB
        + (uint32_t)((lane >> 3) & 1) * 16;

    // prorated contiguous tile range over 152 CTAs
    const int tStart = (int)(((long long)blockIdx.x * TILES_TOTAL) / NSM);
    const int tEnd   = (int)(((long long)(blockIdx.x + 1) * TILES_TOTAL) / NSM);

    int prev_strip = -1;

    for (int t = tStart; t < tEnd; ++t) {
        const int strip = t / OH;              // 0..31 : (n, half)
        const int oh    = t - strip * OH;      // row within strip
        const int n     = strip >> 1;
        const int ow0   = (strip & 1) ? (OW - 128) : 0;

        // ---- strip entry: stage planes oh..oh+2 (120 tasks, 12 warps) ----
        if (strip != prev_strip) {
            #pragma unroll 1
            for (int j = 0; j < 10; ++j) {
                int tk = wid + NWARPS * j;
                if (tk >= 120) break;
                int pl  = tk / 40;
                int r   = tk - pl * 40;
                int oct = r / 5;
                int cg  = r - oct * 5;
                stage_task(x, n, oh + pl, ow0, oct, cg, lane, sb);
            }
            BAR_ALL();
            prev_strip = strip;
        }
        // invariant: planes oh, oh+1, oh+2 staged & visible

        const bool next_same = (t + 1 < tEnd) && (oh + 1 < OH);

        if (consumer) {
            // ---- MMA: warp tile 32px x 64co; software-pipelined fragments ----
            uint32_t acc[2][8][2];
            #pragma unroll
            for (int mi = 0; mi < 2; ++mi)
                #pragma unroll
                for (int nt = 0; nt < 8; ++nt) {
                    acc[mi][nt][0] = 0u;
                    acc[mi][nt][1] = 0u;
                }

            // fragment double buffer: [buf][0]=a0, [1]=a1, [2..5]=bf[0..3]
            uint32_t fr[2][6][4];

            // preload kp=0, ks=0 into buf 0  (kh=0, kw=0)
            uint32_t aKp = sb + OFF_S + (uint32_t)(oh & 3) * S_PLANEB + aCol;
            uint32_t kB  = 0;
            LDSM_X4(fr[0][0], aKp);
            LDSM_X4(fr[0][1], aKp + 16 * S_COLB);
            #pragma unroll
            for (int ntp = 0; ntp < 4; ++ntp)
                LDSM_X4(fr[0][2 + ntp], bBase + (uint32_t)ntp * 16 * W_ROWB);

            #pragma unroll 1
            for (int kp = 0; kp < KPOS; ++kp) {
                // next kp's bases (harmless garbage when kp==8; load is guarded)
                const int kpn = kp + 1;
                const int khn = kpn / 3, kwn = kpn - 3 * khn;
                const uint32_t aKpN = sb + OFF_S + (uint32_t)((oh + khn) & 3) * S_PLANEB
                                    + aCol + (uint32_t)kwn * S_COLB;
                const uint32_t kBN  = (uint32_t)(kpn * 64) * 2;

                #pragma unroll
                for (int ks = 0; ks < 4; ++ks) {
                    const int cur = ks & 1;
                    const int nxt = cur ^ 1;
                    // issue next step's fragment loads before this step's MMAs
                    if (ks < 3) {
                        const uint32_t o = (uint32_t)(ks + 1) * 32;
                        LDSM_X4(fr[nxt][0], aKp + o);
                        LDSM_X4(fr[nxt][1], aKp + o + 16 * S_COLB);
                        #pragma unroll
                        for (int ntp = 0; ntp < 4; ++ntp)
                            LDSM_X4(fr[nxt][2 + ntp],
                                    bBase + (uint32_t)ntp * 16 * W_ROWB + kB + o);
                    } else if (kp < KPOS - 1) {
                        LDSM_X4(fr[nxt][0], aKpN);
                        LDSM_X4(fr[nxt][1], aKpN + 16 * S_COLB);
                        #pragma unroll
                        for (int ntp = 0; ntp < 4; ++ntp)
                            LDSM_X4(fr[nxt][2 + ntp],
                                    bBase + (uint32_t)ntp * 16 * W_ROWB + kBN);
                    }
                    // MMAs on current buffer (loaded a full step earlier)
                    #pragma unroll
                    for (int ntp = 0; ntp < 4; ++ntp) {
                        mma_f16(acc[0][2 * ntp + 0], fr[cur][0], &fr[cur][2 + ntp][0]);
                        mma_f16(acc[0][2 * ntp + 1], fr[cur][0], &fr[cur][2 + ntp][2]);
                        mma_f16(acc[1][2 * ntp + 0], fr[cur][1], &fr[cur][2 + ntp][0]);
                        mma_f16(acc[1][2 * ntp + 1], fr[cur][1], &fr[cur][2 + ntp][2]);
                    }
                }
                aKp = aKpN;
                kB  = kBN;
            }

            // ---- epilogue: half2 bias + min over this warp's 64 co ----
            float v4[4];  // [mi*2 + h]
            #pragma unroll
            for (int mi = 0; mi < 2; ++mi) {
                __half2 h0 = __floats2half2_rn(6.5e4f, 6.5e4f);
                __half2 h1 = h0;
                #pragma unroll
                for (int nt = 0; nt < 8; ++nt) {
                    h0 = __hmin2(h0, __hadd2(*(__half2*)&acc[mi][nt][0], bh[nt]));
                    h1 = __hmin2(h1, __hadd2(*(__half2*)&acc[mi][nt][1], bh[nt]));
                }
                float2 f0 = __half22float2(h0);
                float2 f1 = __half22float2(h1);
                v4[mi * 2 + 0] = fminf(f0.x, f0.y);
                v4[mi * 2 + 1] = fminf(f1.x, f1.y);
            }
            #pragma unroll
            for (int j = 0; j < 4; ++j) {
                v4[j] = fminf(v4[j], __shfl_xor_sync(0xFFFFFFFFu, v4[j], 1));
                v4[j] = fminf(v4[j], __shfl_xor_sync(0xFFFFFFFFu, v4[j], 2));
            }
            if ((lane & 3) == 0) {
                int row = lane >> 2;
                #pragma unroll
                for (int mi = 0; mi < 2; ++mi) {
                    int px0 = wm * 32 + mi * 16 + row;
                    min_sm[px0 * 2 + wn]       = v4[mi * 2 + 0];
                    min_sm[(px0 + 8) * 2 + wn] = v4[mi * 2 + 1];
                }
            }
            // pair barrier: only the two co-half warps of this pixel group
            BAR_PAIR(wm);
            // split the 32 output pixels between the two pair warps (16 each)
            if (lane < 16) {
                int px = wm * 32 + wn * 16 + lane;
                float2 q = *(const float2*)(min_sm + px * 2);
                float m = fminf(q.x, q.y);
                out[((size_t)n * OH + oh) * OW + ow0 + px] = tanhf(tanhf(m));
            }
        } else {
            // ---- producers (4 warps): stage plane oh+3 (10 tasks/warp) ----
            if (next_same) {
                const int pw = wid - 8;
                #pragma unroll
                for (int j = 0; j < 10; ++j) {
                    int tk  = pw + 4 * j;     // 0..39
                    int oct = tk / 5;
                    int cg  = tk - oct * 5;
                    stage_task(x, n, oh + 3, ow0, oct, cg, lane, sb);
                }
            }
        }

        BAR_ALL();  // plane oh+3 visible; min_sm reads done; ring slot retire
    }
}

extern "C" void kernel_launch(void* const* d_in, const int* in_sizes, int n_in,
                              void* d_out, int out_size)
{
    const float* x    = (const float*)d_in[0];
    const float* wgt  = (const float*)d_in[1];
    const float* bias = (const float*)d_in[2];
    float* out        = (float*)d_out;

    cudaFuncSetAttribute(conv_min_tanh_sp,
                         cudaFuncAttributeMaxDynamicSharedMemorySize, SMEM_TOTAL);
    conv_min_tanh_sp<<<NSM, THREADS, SMEM_TOTAL>>>(x, wgt, bias, out);
}